// round 1
// baseline (speedup 1.0000x reference)
#include <cuda_runtime.h>
#include <math.h>

// Fixed problem shape (from reference): B=1024, T=16384, fp32.
#define T_DIM 16384
#define VAR_EPS 1e-5f
#define THREADS 512

// Scratch for per-row losses (no device allocation allowed).
__device__ float g_row_loss[4096];  // headroom if B differs slightly

struct Sums {
    float sp, st, spp, stt, spt;
};

__device__ __forceinline__ Sums warp_reduce(Sums s) {
    #pragma unroll
    for (int off = 16; off > 0; off >>= 1) {
        s.sp  += __shfl_down_sync(0xFFFFFFFFu, s.sp,  off);
        s.st  += __shfl_down_sync(0xFFFFFFFFu, s.st,  off);
        s.spp += __shfl_down_sync(0xFFFFFFFFu, s.spp, off);
        s.stt += __shfl_down_sync(0xFFFFFFFFu, s.stt, off);
        s.spt += __shfl_down_sync(0xFFFFFFFFu, s.spt, off);
    }
    return s;
}

__global__ __launch_bounds__(THREADS, 2)
void pearson_row_kernel(const float* __restrict__ pred,
                        const float* __restrict__ target) {
    const int row = blockIdx.x;
    const float4* __restrict__ p4 =
        reinterpret_cast<const float4*>(pred   + (long long)row * T_DIM);
    const float4* __restrict__ t4 =
        reinterpret_cast<const float4*>(target + (long long)row * T_DIM);

    const int n4 = T_DIM / 4;  // 4096 float4 per row
    Sums s = {0.f, 0.f, 0.f, 0.f, 0.f};

    // Each of 512 threads processes 8 float4 pairs.
    #pragma unroll
    for (int i = threadIdx.x; i < n4; i += THREADS) {
        float4 p = p4[i];
        float4 t = t4[i];
        s.sp  += p.x + p.y + p.z + p.w;
        s.st  += t.x + t.y + t.z + t.w;
        s.spp += p.x * p.x + p.y * p.y + p.z * p.z + p.w * p.w;
        s.stt += t.x * t.x + t.y * t.y + t.z * t.z + t.w * t.w;
        s.spt += p.x * t.x + p.y * t.y + p.z * t.z + p.w * t.w;
    }

    // Intra-warp reduce
    s = warp_reduce(s);

    // Cross-warp reduce via shared memory
    __shared__ Sums warp_sums[THREADS / 32];
    const int lane = threadIdx.x & 31;
    const int wid  = threadIdx.x >> 5;
    if (lane == 0) warp_sums[wid] = s;
    __syncthreads();

    if (wid == 0) {
        Sums z = {0.f, 0.f, 0.f, 0.f, 0.f};
        if (lane < THREADS / 32) z = warp_sums[lane];
        z = warp_reduce(z);
        if (lane == 0) {
            const float T  = (float)T_DIM;
            const float sp  = z.spp - z.sp * z.sp / T;   // centered sum of squares
            const float st  = z.stt - z.st * z.st / T;
            const float num = z.spt - z.sp * z.st / T;
            const float var_p = sp / (T - 1.0f);
            const float var_t = st / (T - 1.0f);
            const float denom = sqrtf(sp * st);
            const float safe  = (denom > 0.f) ? denom : 1.0f;
            const float corr  = num / safe;
            const bool valid = (var_p > VAR_EPS) && (var_t > VAR_EPS) &&
                               (denom > 0.f) && !isnan(corr);
            g_row_loss[blockIdx.x] = valid ? (1.0f - corr) : 1.0f;
        }
    }
}

// Deterministic final reduction of B per-row losses -> mean, single block.
__global__ __launch_bounds__(256)
void pearson_final_kernel(float* __restrict__ out, int B) {
    float acc = 0.f;
    for (int i = threadIdx.x; i < B; i += 256) acc += g_row_loss[i];

    #pragma unroll
    for (int off = 16; off > 0; off >>= 1)
        acc += __shfl_down_sync(0xFFFFFFFFu, acc, off);

    __shared__ float ws[8];
    const int lane = threadIdx.x & 31;
    const int wid  = threadIdx.x >> 5;
    if (lane == 0) ws[wid] = acc;
    __syncthreads();
    if (wid == 0) {
        float v = (lane < 8) ? ws[lane] : 0.f;
        #pragma unroll
        for (int off = 4; off > 0; off >>= 1)
            v += __shfl_down_sync(0xFFFFFFFFu, v, off);
        if (lane == 0) out[0] = v / (float)B;
    }
}

extern "C" void kernel_launch(void* const* d_in, const int* in_sizes, int n_in,
                              void* d_out, int out_size) {
    const float* pred   = (const float*)d_in[0];
    const float* target = (const float*)d_in[1];
    float* out = (float*)d_out;

    const int B = in_sizes[0] / T_DIM;  // 1024

    pearson_row_kernel<<<B, THREADS>>>(pred, target);
    pearson_final_kernel<<<1, 256>>>(out, B);
}